// round 1
// baseline (speedup 1.0000x reference)
#include <cuda_runtime.h>
#include <math.h>

// Problem constants (fixed shapes from the reference)
#define GAMMA_F 1.4f
#define EPS_F   1e-6f
constexpr int B_  = 16;
constexpr int K_  = 64;
constexpr int NT_ = 128;
constexpr int NX_ = 256;
constexpr int NI_ = K_ - 1;           // 63 interfaces per batch
constexpr int N_NEWTON = 20;

// Scratch for the star-state wave speeds (allocation-free: __device__ globals)
__device__ float g_speed_left [B_ * NI_];
__device__ float g_speed_right[B_ * NI_];

// ---------------------------------------------------------------------------
// Kernel 1: per-interface Riemann star-pressure Newton solve -> wave speeds
// 1008 threads total; latency-bound but tiny.
// ---------------------------------------------------------------------------
__device__ __forceinline__ void wave_f_df(float p, float pK, float AK, float BK,
                                          float cK, float& f, float& df) {
    const float gm1 = 0.4f;
    const float exp_rare = gm1 / (2.0f * GAMMA_F);            // 1/7
    const float neg_exp  = -(GAMMA_F + 1.0f) / (2.0f * GAMMA_F); // -6/7

    float denom    = fmaxf(p + BK, EPS_F);
    float sqrt_AoD = sqrtf(fmaxf(AK / denom, EPS_F));
    float f_shock  = (p - pK) * sqrt_AoD;
    float df_shock = sqrt_AoD * (1.0f - (p - pK) / (2.0f * denom));

    float p_ratio = fmaxf(p / fmaxf(pK, EPS_F), EPS_F);
    float f_rare  = 2.0f * cK / gm1 * (powf(p_ratio, exp_rare) - 1.0f);
    float df_rare = cK / (GAMMA_F * fmaxf(pK, EPS_F)) * powf(p_ratio, neg_exp);

    bool is_shock = p > pK;
    f  = is_shock ? f_shock  : f_rare;
    df = is_shock ? df_shock : df_rare;
}

__global__ void riemann_speeds_kernel(const float* __restrict__ ks,
                                      const float* __restrict__ ks_v,
                                      const float* __restrict__ ks_p) {
    int i = blockIdx.x * blockDim.x + threadIdx.x;
    if (i >= B_ * NI_) return;
    int b = i / NI_;
    int j = i - b * NI_;

    const float gm1 = 0.4f;
    const float gp1 = 2.4f;
    const float exp_rare = gm1 / (2.0f * GAMMA_F);  // 1/7

    float rho_L = ks  [b * K_ + j];
    float rho_R = ks  [b * K_ + j + 1];
    float u_L   = ks_v[b * K_ + j];
    float u_R   = ks_v[b * K_ + j + 1];
    float p_L   = ks_p[b * K_ + j];
    float p_R   = ks_p[b * K_ + j + 1];

    float c_L = sqrtf(fmaxf(GAMMA_F * p_L / fmaxf(rho_L, EPS_F), EPS_F));
    float c_R = sqrtf(fmaxf(GAMMA_F * p_R / fmaxf(rho_R, EPS_F), EPS_F));
    float A_L = 2.0f / (gp1 * fmaxf(rho_L, EPS_F));
    float A_R = 2.0f / (gp1 * fmaxf(rho_R, EPS_F));
    float B_L = gm1 / gp1 * p_L;
    float B_R = gm1 / gp1 * p_R;

    // Two-rarefaction initial guess
    float num = c_L + c_R - 0.5f * gm1 * (u_R - u_L);
    float den = c_L / powf(fmaxf(p_L, EPS_F), exp_rare)
              + c_R / powf(fmaxf(p_R, EPS_F), exp_rare);
    float p_star = fmaxf(powf(num / den, 1.0f / exp_rare), EPS_F);

    float du = u_R - u_L;
    #pragma unroll 1
    for (int it = 0; it < N_NEWTON; ++it) {
        float fL, dfL, fR, dfR;
        wave_f_df(p_star, p_L, A_L, B_L, c_L, fL, dfL);
        wave_f_df(p_star, p_R, A_R, B_R, c_R, fR, dfR);
        float residual = fL + fR + du;
        float jacobian = fmaxf(dfL + dfR, EPS_F);
        p_star = fmaxf(p_star - residual / jacobian, EPS_F);
    }

    const float gp1_o_2g = gp1 / (2.0f * GAMMA_F);
    float sig1 = u_L - c_L * sqrtf(fmaxf(1.0f + gp1_o_2g * (p_star / fmaxf(p_L, EPS_F) - 1.0f), EPS_F));
    float speed_left = (p_star > p_L) ? sig1 : (u_L - c_L);
    float sig3 = u_R + c_R * sqrtf(fmaxf(1.0f + gp1_o_2g * (p_star / fmaxf(p_R, EPS_F) - 1.0f), EPS_F));
    float speed_right = (p_star > p_R) ? sig3 : (u_R + c_R);

    g_speed_left [i] = speed_left;
    g_speed_right[i] = speed_right;
}

// ---------------------------------------------------------------------------
// Kernel 2: bias field. One thread per float4 of the contiguous K axis.
// 16 threads per (b,t,x) point; each block covers exactly one batch b.
// Pure streaming stores -> HBM-write-bound.
// ---------------------------------------------------------------------------
constexpr int THREADS = 256;
constexpr int QUADS_PER_POINT = K_ / 4;                 // 16
constexpr int BLOCKS_PER_B = (NT_ * NX_ * QUADS_PER_POINT) / THREADS; // 2048

__global__ __launch_bounds__(THREADS)
void bias_kernel(const float* __restrict__ xs,
                 const float* __restrict__ pieces_mask,
                 const float* __restrict__ t_coords,
                 const float* __restrict__ x_coords,
                 float* __restrict__ out) {
    __shared__ float s_sl[NI_];
    __shared__ float s_sr[NI_];
    __shared__ float s_xd[NI_];
    __shared__ float s_m [K_];

    int b = blockIdx.x / BLOCKS_PER_B;

    int t = threadIdx.x;
    if (t < NI_) {
        s_sl[t] = g_speed_left [b * NI_ + t];
        s_sr[t] = g_speed_right[b * NI_ + t];
        s_xd[t] = xs[b * (K_ + 1) + t + 1];   // x_d[j] = xs[b, j+1]
    }
    if (t < K_) s_m[t] = pieces_mask[b * K_ + t];
    __syncthreads();

    int gtid = blockIdx.x * THREADS + threadIdx.x;
    int pos  = gtid >> 4;        // flat (b*NT + t)*NX + x
    int q    = gtid & 15;        // which float4 along K
    int k0   = q << 2;

    float tt = __ldg(&t_coords[pos]);
    float xx = __ldg(&x_coords[pos]);
    float inv_t = __fdividef(1.0f, tt + EPS_F);

    float vals[4];
    float xi_prev = (k0 > 0) ? (xx - s_xd[k0 - 1]) * inv_t : 0.0f;

    #pragma unroll
    for (int kk = 0; kk < 4; ++kk) {
        int k = k0 + kk;
        float pen = 0.0f;
        float xi_k = 0.0f;
        if (k < NI_) {
            xi_k = (xx - s_xd[k]) * inv_t;
            pen += fmaxf(xi_k - s_sr[k], 0.0f);     // left-running penalty
        }
        if (k > 0) {
            pen += fmaxf(s_sl[k - 1] - xi_prev, 0.0f); // right-running penalty
        }
        float m = s_m[k];
        vals[kk] = -pen * m + ((m == 0.0f) ? -1e9f : 0.0f);
        xi_prev = xi_k;
    }

    float4 o = make_float4(vals[0], vals[1], vals[2], vals[3]);
    // Streaming store: zero reuse, keep it out of L2's way as much as possible
    __stcs(reinterpret_cast<float4*>(out + (size_t)pos * K_ + k0), o);
}

// ---------------------------------------------------------------------------
// Launch
// Inputs (metadata order): 0:xs 1:ks 2:ks_v 3:ks_p 4:pieces_mask 5:t_coords 6:x_coords
// ---------------------------------------------------------------------------
extern "C" void kernel_launch(void* const* d_in, const int* in_sizes, int n_in,
                              void* d_out, int out_size) {
    const float* xs          = (const float*)d_in[0];
    const float* ks          = (const float*)d_in[1];
    const float* ks_v        = (const float*)d_in[2];
    const float* ks_p        = (const float*)d_in[3];
    const float* pieces_mask = (const float*)d_in[4];
    const float* t_coords    = (const float*)d_in[5];
    const float* x_coords    = (const float*)d_in[6];
    float* out = (float*)d_out;

    int n_if = B_ * NI_;
    riemann_speeds_kernel<<<(n_if + 255) / 256, 256>>>(ks, ks_v, ks_p);

    int total_blocks = B_ * BLOCKS_PER_B;   // 32768
    bias_kernel<<<total_blocks, THREADS>>>(xs, pieces_mask, t_coords, x_coords, out);
}

// round 3
// speedup vs baseline: 3.4189x; 3.4189x over previous
#include <cuda_runtime.h>
#include <math.h>

#define GAMMA_F 1.4f
#define EPS_F   1e-6f
constexpr int B_  = 16;
constexpr int K_  = 64;
constexpr int NT_ = 128;
constexpr int NX_ = 256;
constexpr int NI_ = K_ - 1;           // 63 interfaces per batch
constexpr int N_NEWTON = 20;

// Scratch for the star-state wave speeds (allocation-free: __device__ globals)
__device__ float g_speed_left [B_ * NI_];
__device__ float g_speed_right[B_ * NI_];

// MUFU transcendentals via inline PTX (no dependence on libm lowering)
__device__ __forceinline__ float f_lg2(float x) {
    float r;
    asm("lg2.approx.f32 %0, %1;" : "=f"(r) : "f"(x));
    return r;
}
__device__ __forceinline__ float f_ex2(float x) {
    float r;
    asm("ex2.approx.f32 %0, %1;" : "=f"(r) : "f"(x));
    return r;
}
__device__ __forceinline__ float fast_pow(float x, float e) {
    return f_ex2(e * f_lg2(x));
}

// ---------------------------------------------------------------------------
// Kernel 1: per-interface Riemann star-pressure Newton solve -> wave speeds.
// 1008 threads; latency-bound. MUFU-based pow (plenty of accuracy headroom:
// Newton is self-correcting and threshold is 1e-3).
// ---------------------------------------------------------------------------
__global__ void riemann_speeds_kernel(const float* __restrict__ ks,
                                      const float* __restrict__ ks_v,
                                      const float* __restrict__ ks_p) {
    int i = blockIdx.x * blockDim.x + threadIdx.x;
    if (i >= B_ * NI_) return;
    int b = i / NI_;
    int j = i - b * NI_;

    const float gm1 = 0.4f;
    const float gp1 = 2.4f;
    const float exp_rare = gm1 / (2.0f * GAMMA_F);               // 1/7
    const float neg_exp  = -(GAMMA_F + 1.0f) / (2.0f * GAMMA_F); // -6/7

    float rho_L = ks  [b * K_ + j];
    float rho_R = ks  [b * K_ + j + 1];
    float u_L   = ks_v[b * K_ + j];
    float u_R   = ks_v[b * K_ + j + 1];
    float p_L   = ks_p[b * K_ + j];
    float p_R   = ks_p[b * K_ + j + 1];

    float pLc = fmaxf(p_L, EPS_F);
    float pRc = fmaxf(p_R, EPS_F);

    float c_L = sqrtf(fmaxf(GAMMA_F * p_L / fmaxf(rho_L, EPS_F), EPS_F));
    float c_R = sqrtf(fmaxf(GAMMA_F * p_R / fmaxf(rho_R, EPS_F), EPS_F));
    float A_L = 2.0f / (gp1 * fmaxf(rho_L, EPS_F));
    float A_R = 2.0f / (gp1 * fmaxf(rho_R, EPS_F));
    float B_L = gm1 / gp1 * p_L;
    float B_R = gm1 / gp1 * p_R;
    float invpL = __fdividef(1.0f, pLc);
    float invpR = __fdividef(1.0f, pRc);
    float cg_L  = c_L * invpL * (1.0f / GAMMA_F);   // c_K/(GAMMA*p_K)
    float cg_R  = c_R * invpR * (1.0f / GAMMA_F);
    float tfc_L = 2.0f * c_L / gm1;                 // 2 c / (g-1) = 5c
    float tfc_R = 2.0f * c_R / gm1;

    // Two-rarefaction initial guess: ((cL+cR-gm1/2*du)/(cL/pL^{1/7}+cR/pR^{1/7}))^7
    float du  = u_R - u_L;
    float num = c_L + c_R - 0.5f * gm1 * du;
    float den = c_L * fast_pow(pLc, -exp_rare) + c_R * fast_pow(pRc, -exp_rare);
    float r   = __fdividef(num, den);
    float r2  = r * r;
    float r4  = r2 * r2;
    float p_star = fmaxf(r4 * r2 * r, EPS_F);       // r^7

    #pragma unroll 1
    for (int it = 0; it < N_NEWTON; ++it) {
        float fL, dfL, fR, dfR;
        // Left wave
        {
            float denom    = fmaxf(p_star + B_L, EPS_F);
            float sqrt_AoD = sqrtf(fmaxf(__fdividef(A_L, denom), EPS_F));
            float dl       = p_star - p_L;
            float f_shock  = dl * sqrt_AoD;
            float df_shock = sqrt_AoD * (1.0f - dl * __fdividef(0.5f, denom));
            float pratio   = fmaxf(p_star * invpL, EPS_F);
            float l2       = f_lg2(pratio);
            float f_rare   = tfc_L * (f_ex2(exp_rare * l2) - 1.0f);
            float df_rare  = cg_L * f_ex2(neg_exp * l2);
            bool  shock    = p_star > p_L;
            fL  = shock ? f_shock  : f_rare;
            dfL = shock ? df_shock : df_rare;
        }
        // Right wave
        {
            float denom    = fmaxf(p_star + B_R, EPS_F);
            float sqrt_AoD = sqrtf(fmaxf(__fdividef(A_R, denom), EPS_F));
            float dr       = p_star - p_R;
            float f_shock  = dr * sqrt_AoD;
            float df_shock = sqrt_AoD * (1.0f - dr * __fdividef(0.5f, denom));
            float pratio   = fmaxf(p_star * invpR, EPS_F);
            float l2       = f_lg2(pratio);
            float f_rare   = tfc_R * (f_ex2(exp_rare * l2) - 1.0f);
            float df_rare  = cg_R * f_ex2(neg_exp * l2);
            bool  shock    = p_star > p_R;
            fR  = shock ? f_shock  : f_rare;
            dfR = shock ? df_shock : df_rare;
        }
        float residual = fL + fR + du;
        float jacobian = fmaxf(dfL + dfR, EPS_F);
        p_star = fmaxf(p_star - __fdividef(residual, jacobian), EPS_F);
    }

    const float gp1_o_2g = gp1 / (2.0f * GAMMA_F);
    float sig1 = u_L - c_L * sqrtf(fmaxf(1.0f + gp1_o_2g * (p_star * invpL - 1.0f), EPS_F));
    float speed_left = (p_star > p_L) ? sig1 : (u_L - c_L);
    float sig3 = u_R + c_R * sqrtf(fmaxf(1.0f + gp1_o_2g * (p_star * invpR - 1.0f), EPS_F));
    float speed_right = (p_star > p_R) ? sig3 : (u_R + c_R);

    g_speed_left [i] = speed_left;
    g_speed_right[i] = speed_right;
}

// ---------------------------------------------------------------------------
// Kernel 2: bias field.
// Each thread owns one FIXED float4-quad of K and loops over ITER positions;
// all per-k tables live in registers (loaded once via a shared-memory stage).
// Hot loop per 64B stored: 2 LDG.32 + ~36 FMA/ALU + 1 STG.128 (streaming).
// Algebra: relu((x-xd)/te - sr) = relu(x - xd - sr*te) / te   (te > 0),
// so the divide is hoisted and each penalty is FMA+RELU.
// Edge k=0 / k=63 handled branchlessly via +-1e30 sentinel pads.
// ---------------------------------------------------------------------------
constexpr int THREADS = 256;
constexpr int ITER = 16;
constexpr int POS_PER_ITER  = THREADS / 16;                 // 16 positions
constexpr int POS_PER_BLOCK = POS_PER_ITER * ITER;          // 256
constexpr int BLOCKS_PER_B  = (NT_ * NX_) / POS_PER_BLOCK;  // 128

__global__ __launch_bounds__(THREADS)
void bias_kernel(const float* __restrict__ xs,
                 const float* __restrict__ pieces_mask,
                 const float* __restrict__ t_coords,
                 const float* __restrict__ x_coords,
                 float* __restrict__ out) {
    __shared__ float s_xd[K_];   // s_xd[k] = xs[b,k+1] for k<63; s_xd[63] = 0 (pad)
    __shared__ float s_sl[NI_];
    __shared__ float s_sr[K_];   // s_sr[63] = +1e30 (pad: kills pen_left at k=63)
    __shared__ float s_m [K_];

    int b        = blockIdx.x >> 7;        // / BLOCKS_PER_B (=128)
    int blockInB = blockIdx.x & (BLOCKS_PER_B - 1);

    int t = threadIdx.x;
    if (t < NI_) {
        s_sl[t] = g_speed_left [b * NI_ + t];
        s_sr[t] = g_speed_right[b * NI_ + t];
        s_xd[t] = xs[b * (K_ + 1) + t + 1];
    }
    if (t == NI_) { s_xd[NI_] = 0.0f; s_sr[NI_] = 1e30f; }
    if (t < K_) s_m[t] = pieces_mask[b * K_ + t];
    __syncthreads();

    int q  = t & 15;
    int k0 = q << 2;

    // Per-thread register tables
    float xda[5];                          // xd[k0-1 .. k0+3]
    float slv[4], srv[4], negm[4], b0[4];  // sl[k-1], sr[k], -m[k], bias0[k]
    xda[0] = (k0 == 0) ? 0.0f : s_xd[k0 - 1];
    slv[0] = (k0 == 0) ? -1e30f : s_sl[k0 - 1];   // sentinel: pen_right(k=0)=0
    #pragma unroll
    for (int i = 1; i < 5; ++i) xda[i] = s_xd[k0 + i - 1];
    #pragma unroll
    for (int kk = 1; kk < 4; ++kk) slv[kk] = s_sl[k0 + kk - 1];
    #pragma unroll
    for (int kk = 0; kk < 4; ++kk) {
        srv[kk] = s_sr[k0 + kk];
        float m = s_m[k0 + kk];
        negm[kk] = -m;
        b0[kk]   = (m == 0.0f) ? -1e9f : 0.0f;
    }

    size_t posBase = (size_t)b * (NT_ * NX_)
                   + (size_t)blockInB * POS_PER_BLOCK
                   + (t >> 4);
    const float* tp = t_coords + posBase;
    const float* xp = x_coords + posBase;
    float* op = out + posBase * K_ + k0;

    #pragma unroll
    for (int it = 0; it < ITER; ++it) {
        int off = it * POS_PER_ITER;
        float tt = __ldg(tp + off);
        float xx = __ldg(xp + off);
        float te  = tt + EPS_F;
        float inv = __fdividef(1.0f, te);

        float vals[4];
        #pragma unroll
        for (int kk = 0; kk < 4; ++kk) {
            float pl = fmaxf(fmaf(-srv[kk], te, xx - xda[kk + 1]), 0.0f);
            float pr = fmaxf(fmaf( slv[kk], te, xda[kk] - xx),     0.0f);
            vals[kk] = fmaf((pl + pr) * inv, negm[kk], b0[kk]);
        }
        __stcs(reinterpret_cast<float4*>(op + (size_t)off * K_),
               make_float4(vals[0], vals[1], vals[2], vals[3]));
    }
}

// ---------------------------------------------------------------------------
// Launch. Inputs: 0:xs 1:ks 2:ks_v 3:ks_p 4:pieces_mask 5:t_coords 6:x_coords
// ---------------------------------------------------------------------------
extern "C" void kernel_launch(void* const* d_in, const int* in_sizes, int n_in,
                              void* d_out, int out_size) {
    const float* xs          = (const float*)d_in[0];
    const float* ks          = (const float*)d_in[1];
    const float* ks_v        = (const float*)d_in[2];
    const float* ks_p        = (const float*)d_in[3];
    const float* pieces_mask = (const float*)d_in[4];
    const float* t_coords    = (const float*)d_in[5];
    const float* x_coords    = (const float*)d_in[6];
    float* out = (float*)d_out;

    int n_if = B_ * NI_;
    riemann_speeds_kernel<<<(n_if + 255) / 256, 256>>>(ks, ks_v, ks_p);

    int total_blocks = B_ * BLOCKS_PER_B;   // 2048
    bias_kernel<<<total_blocks, THREADS>>>(xs, pieces_mask, t_coords, x_coords, out);
}